// round 1
// baseline (speedup 1.0000x reference)
#include <cuda_runtime.h>
#include <cuda_bf16.h>
#include <cstdint>

// Problem constants
#define BB 2
#define LL 2048
#define DD 1024
#define NH 16
#define HD 64
#define MM (BB*LL)      // 4096
#define N3 (3*DD)       // 3072
#define KK DD           // 1024

// Scratch for qkv = x @ W^T + b : [4096, 3072] fp32 (~50 MB, static device global)
__device__ float g_qkv[(size_t)MM * N3];

// ---------------------------------------------------------------------------
// Kernel 1: QKV GEMM.  C[m,n] = sum_k x[m,k] * W[n,k] + b[n]
// 128x128x16 tile, 256 threads, 8x8 per-thread microtile.
// ---------------------------------------------------------------------------
__global__ __launch_bounds__(256) void qkv_gemm_kernel(
    const float* __restrict__ x,     // [MM, KK]
    const float* __restrict__ W,     // [N3, KK]
    const float* __restrict__ bias,  // [N3]
    float* __restrict__ C)           // [MM, N3]
{
    __shared__ float As[16][132];
    __shared__ float Bs[16][132];

    const int bm = blockIdx.y * 128;
    const int bn = blockIdx.x * 128;
    const int tid = threadIdx.x;
    const int tx = tid & 15;   // 0..15 -> column group
    const int ty = tid >> 4;   // 0..15 -> row group

    float acc[8][8];
#pragma unroll
    for (int i = 0; i < 8; i++)
#pragma unroll
        for (int j = 0; j < 8; j++) acc[i][j] = 0.f;

    for (int k0 = 0; k0 < KK; k0 += 16) {
        // Load A tile (128x16) and B tile (128x16), transposed into smem.
        // 512 float4 per tile, 2 per thread.
#pragma unroll
        for (int i = 0; i < 2; i++) {
            int idx = tid * 2 + i;
            int row = idx >> 2;
            int f4  = idx & 3;
            float4 a = *(const float4*)(x + (size_t)(bm + row) * KK + k0 + f4 * 4);
            As[f4 * 4 + 0][row] = a.x;
            As[f4 * 4 + 1][row] = a.y;
            As[f4 * 4 + 2][row] = a.z;
            As[f4 * 4 + 3][row] = a.w;
            float4 b = *(const float4*)(W + (size_t)(bn + row) * KK + k0 + f4 * 4);
            Bs[f4 * 4 + 0][row] = b.x;
            Bs[f4 * 4 + 1][row] = b.y;
            Bs[f4 * 4 + 2][row] = b.z;
            Bs[f4 * 4 + 3][row] = b.w;
        }
        __syncthreads();

#pragma unroll
        for (int k = 0; k < 16; k++) {
            float4 a0 = *(const float4*)&As[k][ty * 4];
            float4 a1 = *(const float4*)&As[k][64 + ty * 4];
            float4 b0 = *(const float4*)&Bs[k][tx * 4];
            float4 b1 = *(const float4*)&Bs[k][64 + tx * 4];
            float a[8] = {a0.x, a0.y, a0.z, a0.w, a1.x, a1.y, a1.z, a1.w};
            float b[8] = {b0.x, b0.y, b0.z, b0.w, b1.x, b1.y, b1.z, b1.w};
#pragma unroll
            for (int i = 0; i < 8; i++)
#pragma unroll
                for (int j = 0; j < 8; j++)
                    acc[i][j] = fmaf(a[i], b[j], acc[i][j]);
        }
        __syncthreads();
    }

    // Epilogue: add bias, store (two float4 per row-sub).
#pragma unroll
    for (int ii = 0; ii < 8; ii++) {
        int r = bm + ((ii < 4) ? (ty * 4 + ii) : (64 + ty * 4 + (ii - 4)));
        int c0 = bn + tx * 4;
        int c1 = bn + 64 + tx * 4;
        float4 v0, v1;
        v0.x = acc[ii][0] + bias[c0 + 0];
        v0.y = acc[ii][1] + bias[c0 + 1];
        v0.z = acc[ii][2] + bias[c0 + 2];
        v0.w = acc[ii][3] + bias[c0 + 3];
        v1.x = acc[ii][4] + bias[c1 + 0];
        v1.y = acc[ii][5] + bias[c1 + 1];
        v1.z = acc[ii][6] + bias[c1 + 2];
        v1.w = acc[ii][7] + bias[c1 + 3];
        *(float4*)(C + (size_t)r * N3 + c0) = v0;
        *(float4*)(C + (size_t)r * N3 + c1) = v1;
    }
}

// ---------------------------------------------------------------------------
// Kernel 2: flash-style attention.
// Grid: (qtile=32, head=16, batch=2), 64 threads. Each thread owns one q row:
// qr[64], o[64], s[64] in registers; K/V tiles (64x64) staged in smem.
// ---------------------------------------------------------------------------
__global__ __launch_bounds__(64) void attn_kernel(
    const float* __restrict__ qkv,   // [MM, N3]
    float* __restrict__ out)         // [MM, DD]
{
    __shared__ float Ks[64][68];
    __shared__ float Vs[64][68];

    const int qtile = blockIdx.x;   // 0..31
    const int h     = blockIdx.y;   // 0..15
    const int b     = blockIdx.z;   // 0..1
    const int t     = threadIdx.x;  // 0..63

    const float scale = 0.125f;     // 1/sqrt(64)
    const int qrow = qtile * 64 + t;

    // Load this thread's q row (scaled) into registers.
    const float* qptr = qkv + ((size_t)(b * LL + qrow)) * N3 + h * HD;
    float qr[64];
#pragma unroll
    for (int d = 0; d < 64; d += 4) {
        float4 v = *(const float4*)(qptr + d);
        qr[d + 0] = v.x * scale;
        qr[d + 1] = v.y * scale;
        qr[d + 2] = v.z * scale;
        qr[d + 3] = v.w * scale;
    }

    float o[64];
#pragma unroll
    for (int d = 0; d < 64; d++) o[d] = 0.f;
    float m = -1e30f;
    float l = 0.f;

    const int cr = t >> 4;   // 0..3  : row offset within pass
    const int cc = t & 15;   // 0..15 : float4 index within row

    for (int kt = 0; kt < LL / 64; kt++) {
        __syncthreads();  // protect previous tile's consumers
        // Cooperative coalesced load of K and V tiles (16 threads per row).
#pragma unroll
        for (int pass = 0; pass < 16; pass++) {
            int row = pass * 4 + cr;
            int kl  = kt * 64 + row;
            const float* kp = qkv + ((size_t)(b * LL + kl)) * N3 + DD + h * HD + cc * 4;
            float4 k4 = *(const float4*)kp;
            float4 v4 = *(const float4*)(kp + DD);
            *(float4*)&Ks[row][cc * 4] = k4;
            *(float4*)&Vs[row][cc * 4] = v4;
        }
        __syncthreads();

        // s[j] = qr . K[j]
        float s[64];
#pragma unroll 2
        for (int j = 0; j < 64; j++) {
            const float4* krow = (const float4*)&Ks[j][0];
            float acc0 = 0.f, acc1 = 0.f, acc2 = 0.f, acc3 = 0.f;
#pragma unroll
            for (int d4 = 0; d4 < 16; d4++) {
                float4 kk = krow[d4];
                acc0 = fmaf(qr[d4 * 4 + 0], kk.x, acc0);
                acc1 = fmaf(qr[d4 * 4 + 1], kk.y, acc1);
                acc2 = fmaf(qr[d4 * 4 + 2], kk.z, acc2);
                acc3 = fmaf(qr[d4 * 4 + 3], kk.w, acc3);
            }
            s[j] = (acc0 + acc1) + (acc2 + acc3);
        }

        // Online softmax update.
        float mt = m;
#pragma unroll
        for (int j = 0; j < 64; j++) mt = fmaxf(mt, s[j]);
        float corr = __expf(m - mt);
        m = mt;
        l *= corr;
#pragma unroll
        for (int d = 0; d < 64; d++) o[d] *= corr;

#pragma unroll 2
        for (int j = 0; j < 64; j++) {
            float p = __expf(s[j] - mt);
            l += p;
            const float4* vrow = (const float4*)&Vs[j][0];
#pragma unroll
            for (int d4 = 0; d4 < 16; d4++) {
                float4 vv = vrow[d4];
                o[d4 * 4 + 0] = fmaf(p, vv.x, o[d4 * 4 + 0]);
                o[d4 * 4 + 1] = fmaf(p, vv.y, o[d4 * 4 + 1]);
                o[d4 * 4 + 2] = fmaf(p, vv.z, o[d4 * 4 + 2]);
                o[d4 * 4 + 3] = fmaf(p, vv.w, o[d4 * 4 + 3]);
            }
        }
    }

    const float inv = 1.f / l;

    // Stage through smem for coalesced global stores.
    __syncthreads();
#pragma unroll
    for (int d = 0; d < 64; d++) Ks[t][d] = o[d] * inv;
    __syncthreads();
#pragma unroll
    for (int pass = 0; pass < 16; pass++) {
        int row = pass * 4 + cr;
        float4 v = *(const float4*)&Ks[row][cc * 4];
        *(float4*)(out + ((size_t)(b * LL + qtile * 64 + row)) * DD + h * HD + cc * 4) = v;
    }
}

// ---------------------------------------------------------------------------
extern "C" void kernel_launch(void* const* d_in, const int* in_sizes, int n_in,
                              void* d_out, int out_size)
{
    const float* x    = (const float*)d_in[0];   // [2, 2048, 1024]
    const float* W    = (const float*)d_in[1];   // [3072, 1024]
    const float* bias = (const float*)d_in[2];   // [3072]
    float* out = (float*)d_out;                  // [2, 2048, 1024]

    float* qkv;
    cudaGetSymbolAddress((void**)&qkv, g_qkv);

    dim3 ggrid(N3 / 128, MM / 128);  // (24, 32)
    qkv_gemm_kernel<<<ggrid, 256>>>(x, W, bias, qkv);

    dim3 agrid(LL / 64, NH, BB);     // (32, 16, 2)
    attn_kernel<<<agrid, 64>>>(qkv, out);
}

// round 2
// speedup vs baseline: 1.0734x; 1.0734x over previous
#include <cuda_runtime.h>
#include <cuda_bf16.h>
#include <cstdint>

// Problem constants
#define BB 2
#define LL 2048
#define DD 1024
#define NH 16
#define HD 64
#define MM (BB*LL)      // 4096
#define N3 (3*DD)       // 3072
#define KK DD           // 1024

typedef unsigned long long u64;

// ---- packed f32x2 helpers (FFMA2 path, sm_103a) ----
__device__ __forceinline__ u64 pack2(float lo, float hi) {
    u64 r; asm("mov.b64 %0, {%1, %2};" : "=l"(r) : "f"(lo), "f"(hi)); return r;
}
__device__ __forceinline__ void unpack2(u64 v, float& lo, float& hi) {
    asm("mov.b64 {%0, %1}, %2;" : "=f"(lo), "=f"(hi) : "l"(v));
}
__device__ __forceinline__ u64 ffma2(u64 a, u64 b, u64 c) {
    u64 d; asm("fma.rn.f32x2 %0, %1, %2, %3;" : "=l"(d) : "l"(a), "l"(b), "l"(c)); return d;
}
__device__ __forceinline__ u64 fmul2(u64 a, u64 b) {
    u64 d; asm("mul.rn.f32x2 %0, %1, %2;" : "=l"(d) : "l"(a), "l"(b)); return d;
}
__device__ __forceinline__ u64 fadd2(u64 a, u64 b) {
    u64 d; asm("add.rn.f32x2 %0, %1, %2;" : "=l"(d) : "l"(a), "l"(b)); return d;
}

// Scratch for qkv = x @ W^T + b : [4096, 3072] fp32
__device__ float g_qkv[(size_t)MM * N3];

// ---------------------------------------------------------------------------
// Kernel 1: QKV GEMM.  C[m,n] = sum_k x[m,k] * W[n,k] + b[n]
// 128x128x16 tile, 256 threads, 8x8 per-thread microtile, FFMA2 math.
// ---------------------------------------------------------------------------
__global__ __launch_bounds__(256) void qkv_gemm_kernel(
    const float* __restrict__ x,     // [MM, KK]
    const float* __restrict__ W,     // [N3, KK]
    const float* __restrict__ bias,  // [N3]
    float* __restrict__ C)           // [MM, N3]
{
    __shared__ float As[16][132];
    __shared__ float Bs[16][132];

    const int bm = blockIdx.y * 128;
    const int bn = blockIdx.x * 128;
    const int tid = threadIdx.x;
    const int tx = tid & 15;   // column group
    const int ty = tid >> 4;   // row group

    // acc2[i][jp] holds the pair (acc[i][2jp], acc[i][2jp+1])
    u64 acc2[8][4];
#pragma unroll
    for (int i = 0; i < 8; i++)
#pragma unroll
        for (int j = 0; j < 4; j++) acc2[i][j] = 0ULL;

    for (int k0 = 0; k0 < KK; k0 += 16) {
#pragma unroll
        for (int i = 0; i < 2; i++) {
            int idx = tid * 2 + i;
            int row = idx >> 2;
            int f4  = idx & 3;
            float4 a = *(const float4*)(x + (size_t)(bm + row) * KK + k0 + f4 * 4);
            As[f4 * 4 + 0][row] = a.x;
            As[f4 * 4 + 1][row] = a.y;
            As[f4 * 4 + 2][row] = a.z;
            As[f4 * 4 + 3][row] = a.w;
            float4 b = *(const float4*)(W + (size_t)(bn + row) * KK + k0 + f4 * 4);
            Bs[f4 * 4 + 0][row] = b.x;
            Bs[f4 * 4 + 1][row] = b.y;
            Bs[f4 * 4 + 2][row] = b.z;
            Bs[f4 * 4 + 3][row] = b.w;
        }
        __syncthreads();

#pragma unroll
        for (int k = 0; k < 16; k++) {
            float4 a0 = *(const float4*)&As[k][ty * 4];
            float4 a1 = *(const float4*)&As[k][64 + ty * 4];
            ulonglong2 b01 = *(const ulonglong2*)&Bs[k][tx * 4];        // pairs (b0,b1),(b2,b3)
            ulonglong2 b23 = *(const ulonglong2*)&Bs[k][64 + tx * 4];   // pairs (b4,b5),(b6,b7)
            u64 ap[8];
            ap[0] = pack2(a0.x, a0.x); ap[1] = pack2(a0.y, a0.y);
            ap[2] = pack2(a0.z, a0.z); ap[3] = pack2(a0.w, a0.w);
            ap[4] = pack2(a1.x, a1.x); ap[5] = pack2(a1.y, a1.y);
            ap[6] = pack2(a1.z, a1.z); ap[7] = pack2(a1.w, a1.w);
#pragma unroll
            for (int i = 0; i < 8; i++) {
                acc2[i][0] = ffma2(ap[i], b01.x, acc2[i][0]);
                acc2[i][1] = ffma2(ap[i], b01.y, acc2[i][1]);
                acc2[i][2] = ffma2(ap[i], b23.x, acc2[i][2]);
                acc2[i][3] = ffma2(ap[i], b23.y, acc2[i][3]);
            }
        }
        __syncthreads();
    }

    // Epilogue: bias add + store, all in packed pairs.
    const int c0 = bn + tx * 4;
    const int c1 = bn + 64 + tx * 4;
    ulonglong2 bb0 = *(const ulonglong2*)(bias + c0);
    ulonglong2 bb1 = *(const ulonglong2*)(bias + c1);
#pragma unroll
    for (int ii = 0; ii < 8; ii++) {
        int r = bm + ((ii < 4) ? (ty * 4 + ii) : (64 + ty * 4 + (ii - 4)));
        ulonglong2 v0, v1;
        v0.x = fadd2(acc2[ii][0], bb0.x);
        v0.y = fadd2(acc2[ii][1], bb0.y);
        v1.x = fadd2(acc2[ii][2], bb1.x);
        v1.y = fadd2(acc2[ii][3], bb1.y);
        *(ulonglong2*)(C + (size_t)r * N3 + c0) = v0;
        *(ulonglong2*)(C + (size_t)r * N3 + c1) = v1;
    }
}

// ---------------------------------------------------------------------------
// Kernel 2: flash-style attention, FFMA2 math.
// Grid: (qtile=16, head=16, batch=2), 128 threads. Each thread owns one q row
// (packed f32x2): qp[32], o[32] u64; K/V tiles (64x64) staged in smem.
// ---------------------------------------------------------------------------
__global__ __launch_bounds__(128) void attn_kernel(
    const float* __restrict__ qkv,   // [MM, N3]
    float* __restrict__ out)         // [MM, DD]
{
    __shared__ float smemf[2 * 64 * 68];   // Ks tile | Vs tile (also reused as store stage)
#define KS(j,d) smemf[(j) * 68 + (d)]
#define VS(j,d) smemf[64 * 68 + (j) * 68 + (d)]

    const int qtile = blockIdx.x;   // 0..15
    const int h     = blockIdx.y;   // 0..15
    const int b     = blockIdx.z;   // 0..1
    const int t     = threadIdx.x;  // 0..127

    const float scale = 0.125f;     // 1/sqrt(64)
    const int qrow = qtile * 128 + t;

    // Load this thread's q row, scaled, as 32 packed pairs.
    const float* qptr = qkv + ((size_t)(b * LL + qrow)) * N3 + h * HD;
    u64 qp[32];
    {
        const u64 sc2 = pack2(scale, scale);
#pragma unroll
        for (int i = 0; i < 16; i++) {
            ulonglong2 v = *(const ulonglong2*)(qptr + i * 4);
            qp[2 * i + 0] = fmul2(v.x, sc2);
            qp[2 * i + 1] = fmul2(v.y, sc2);
        }
    }

    u64 o[32];
#pragma unroll
    for (int i = 0; i < 32; i++) o[i] = 0ULL;   // bit pattern 0 == (0.f, 0.f)
    float m = -1e30f;
    float l = 0.f;

    const int cr = t >> 4;   // 0..7 : row offset within pass
    const int cc = t & 15;   // 0..15: float4 index within row

    for (int kt = 0; kt < LL / 64; kt++) {
        __syncthreads();
        // Cooperative coalesced load of K and V tiles (16 threads/row, 8 rows/pass).
#pragma unroll
        for (int pass = 0; pass < 8; pass++) {
            int row = pass * 8 + cr;
            int kl  = kt * 64 + row;
            const float* kp = qkv + ((size_t)(b * LL + kl)) * N3 + DD + h * HD + cc * 4;
            float4 k4 = *(const float4*)kp;
            float4 v4 = *(const float4*)(kp + DD);
            *(float4*)&KS(row, cc * 4) = k4;
            *(float4*)&VS(row, cc * 4) = v4;
        }
        __syncthreads();

        // s[j] = qr . K[j]   (packed pairs, 4 accumulator chains)
        float s[64];
#pragma unroll 2
        for (int j = 0; j < 64; j++) {
            const ulonglong2* kr = (const ulonglong2*)&KS(j, 0);
            u64 a0 = 0ULL, a1 = 0ULL, a2 = 0ULL, a3 = 0ULL;
#pragma unroll
            for (int q4 = 0; q4 < 16; q4 += 2) {
                ulonglong2 k0 = kr[q4];
                ulonglong2 k1 = kr[q4 + 1];
                a0 = ffma2(qp[2 * q4 + 0], k0.x, a0);
                a1 = ffma2(qp[2 * q4 + 1], k0.y, a1);
                a2 = ffma2(qp[2 * q4 + 2], k1.x, a2);
                a3 = ffma2(qp[2 * q4 + 3], k1.y, a3);
            }
            u64 tsum = fadd2(fadd2(a0, a2), fadd2(a1, a3));
            float lo, hi; unpack2(tsum, lo, hi);
            s[j] = lo + hi;
        }

        // Online softmax update.
        float mt = m;
#pragma unroll
        for (int j = 0; j < 64; j++) mt = fmaxf(mt, s[j]);
        float corr = __expf(m - mt);
        m = mt;
        l *= corr;
        {
            u64 corr2 = pack2(corr, corr);
#pragma unroll
            for (int i = 0; i < 32; i++) o[i] = fmul2(o[i], corr2);
        }

#pragma unroll 2
        for (int j = 0; j < 64; j++) {
            float p = __expf(s[j] - mt);
            l += p;
            u64 pj = pack2(p, p);
            const ulonglong2* vrow = (const ulonglong2*)&VS(j, 0);
#pragma unroll
            for (int q4 = 0; q4 < 16; q4++) {
                ulonglong2 vv = vrow[q4];
                o[2 * q4 + 0] = ffma2(pj, vv.x, o[2 * q4 + 0]);
                o[2 * q4 + 1] = ffma2(pj, vv.y, o[2 * q4 + 1]);
            }
        }
    }

    // Normalize.
    {
        float inv = 1.f / l;
        u64 inv2 = pack2(inv, inv);
#pragma unroll
        for (int i = 0; i < 32; i++) o[i] = fmul2(o[i], inv2);
    }

    // Stage through smem (stride 66 to dodge bank conflicts) for coalesced stores.
    __syncthreads();
#pragma unroll
    for (int i = 0; i < 32; i++)
        *(u64*)&smemf[t * 66 + 2 * i] = o[i];
    __syncthreads();
#pragma unroll
    for (int pass = 0; pass < 16; pass++) {
        int row = pass * 8 + cr;
        u64 lo = *(const u64*)&smemf[row * 66 + cc * 4];
        u64 hi = *(const u64*)&smemf[row * 66 + cc * 4 + 2];
        ulonglong2 v; v.x = lo; v.y = hi;
        *(ulonglong2*)(out + ((size_t)(b * LL + qtile * 128 + row)) * DD + h * HD + cc * 4) = v;
    }
#undef KS
#undef VS
}

// ---------------------------------------------------------------------------
extern "C" void kernel_launch(void* const* d_in, const int* in_sizes, int n_in,
                              void* d_out, int out_size)
{
    const float* x    = (const float*)d_in[0];   // [2, 2048, 1024]
    const float* W    = (const float*)d_in[1];   // [3072, 1024]
    const float* bias = (const float*)d_in[2];   // [3072]
    float* out = (float*)d_out;                  // [2, 2048, 1024]

    float* qkv;
    cudaGetSymbolAddress((void**)&qkv, g_qkv);

    dim3 ggrid(N3 / 128, MM / 128);  // (24, 32)
    qkv_gemm_kernel<<<ggrid, 256>>>(x, W, bias, qkv);

    dim3 agrid(LL / 128, NH, BB);    // (16, 16, 2)
    attn_kernel<<<agrid, 128>>>(qkv, out);
}

// round 4
// speedup vs baseline: 1.2769x; 1.1896x over previous
#include <cuda_runtime.h>
#include <cuda_bf16.h>
#include <cstdint>

// Problem constants
#define BB 2
#define LL 2048
#define DD 1024
#define NH 16
#define HD 64
#define MM (BB*LL)      // 4096
#define N3 (3*DD)       // 3072
#define KK DD           // 1024

typedef unsigned long long u64;
typedef unsigned int u32;

// ---- packed f32x2 helpers (FFMA2 path, sm_103a) ----
__device__ __forceinline__ u64 pack2(float lo, float hi) {
    u64 r; asm("mov.b64 %0, {%1, %2};" : "=l"(r) : "f"(lo), "f"(hi)); return r;
}
__device__ __forceinline__ void unpack2(u64 v, float& lo, float& hi) {
    asm("mov.b64 {%0, %1}, %2;" : "=f"(lo), "=f"(hi) : "l"(v));
}
__device__ __forceinline__ u64 ffma2(u64 a, u64 b, u64 c) {
    u64 d; asm("fma.rn.f32x2 %0, %1, %2, %3;" : "=l"(d) : "l"(a), "l"(b), "l"(c)); return d;
}
__device__ __forceinline__ u64 fmul2(u64 a, u64 b) {
    u64 d; asm("mul.rn.f32x2 %0, %1, %2;" : "=l"(d) : "l"(a), "l"(b)); return d;
}
__device__ __forceinline__ u64 fadd2(u64 a, u64 b) {
    u64 d; asm("add.rn.f32x2 %0, %1, %2;" : "=l"(d) : "l"(a), "l"(b)); return d;
}

// ---- tf32 mma.sync helpers (legacy tensor-core path, works on this target) ----
__device__ __forceinline__ u32 f2tf32(float f) {
    u32 r; asm("cvt.rna.tf32.f32 %0, %1;" : "=r"(r) : "f"(f)); return r;
}
__device__ __forceinline__ void mma_tf32(float& d0, float& d1, float& d2, float& d3,
                                         u32 a0, u32 a1, u32 a2, u32 a3,
                                         u32 b0, u32 b1) {
    asm volatile(
        "mma.sync.aligned.m16n8k8.row.col.f32.tf32.tf32.f32 "
        "{%0,%1,%2,%3}, {%4,%5,%6,%7}, {%8,%9}, {%0,%1,%2,%3};"
        : "+f"(d0), "+f"(d1), "+f"(d2), "+f"(d3)
        : "r"(a0), "r"(a1), "r"(a2), "r"(a3), "r"(b0), "r"(b1));
}

// Scratch for qkv = x @ W^T + b : [4096, 3072] fp32
__device__ float g_qkv[(size_t)MM * N3];

// ---------------------------------------------------------------------------
// Kernel 1: QKV GEMM on mma.sync tf32.
// CTA tile 128x128, K-chunks of 32, 256 threads = 8 warps (2m x 4n).
// Warp tile 64x32 = 4x4 m16n8k8 tiles. D accumulates in registers.
// smem row stride 36 floats -> fragment LDS are bank-conflict-free.
// ---------------------------------------------------------------------------
#define LDS_STRIDE 36

__global__ __launch_bounds__(256) void qkv_gemm_mma(
    const float* __restrict__ x,     // [MM, KK]
    const float* __restrict__ W,     // [N3, KK]
    const float* __restrict__ bias,  // [N3]
    float* __restrict__ C)           // [MM, N3]
{
    __shared__ u32 sX[128 * LDS_STRIDE];   // tf32 bits of x tile [128 m][32 k]
    __shared__ u32 sW[128 * LDS_STRIDE];   // tf32 bits of W tile [128 n][32 k]
    __shared__ float sBias[128];

    const int bm = blockIdx.y * 128;
    const int bn = blockIdx.x * 128;
    const int tid  = threadIdx.x;
    const int wid  = tid >> 5;
    const int lane = tid & 31;
    const int wm = (wid >> 2) * 64;   // warp m offset in CTA tile
    const int wn = (wid & 3) * 32;    // warp n offset

    const int lr = lane >> 2;         // 0..7
    const int lc = lane & 3;          // 0..3

    float d[4][4][4];                  // [m-tile][n-tile][reg]
#pragma unroll
    for (int mt = 0; mt < 4; mt++)
#pragma unroll
        for (int nt = 0; nt < 4; nt++)
#pragma unroll
            for (int r = 0; r < 4; r++) d[mt][nt][r] = 0.f;

    if (tid < 128) sBias[tid] = bias[bn + tid];

    for (int c = 0; c < KK / 32; c++) {
        const int k0 = c * 32;
        // Load 128x32 tiles of x and W, convert to tf32 (rna), store to smem.
        // 1024 float4 per tile, 4 per thread.
#pragma unroll
        for (int i = 0; i < 4; i++) {
            int idx = tid + i * 256;
            int row = idx >> 3;
            int f4  = idx & 7;
            float4 xa = *(const float4*)(x + (size_t)(bm + row) * KK + k0 + f4 * 4);
            float4 wa = *(const float4*)(W + (size_t)(bn + row) * KK + k0 + f4 * 4);
            uint4 xt = make_uint4(f2tf32(xa.x), f2tf32(xa.y), f2tf32(xa.z), f2tf32(xa.w));
            uint4 wt = make_uint4(f2tf32(wa.x), f2tf32(wa.y), f2tf32(wa.z), f2tf32(wa.w));
            *(uint4*)&sX[row * LDS_STRIDE + f4 * 4] = xt;
            *(uint4*)&sW[row * LDS_STRIDE + f4 * 4] = wt;
        }
        __syncthreads();

#pragma unroll
        for (int ks = 0; ks < 4; ks++) {
            const int kk = ks * 8;
            u32 af[4][4];
            u32 bf[4][2];
#pragma unroll
            for (int mt = 0; mt < 4; mt++) {
                const int rb = wm + mt * 16;
                af[mt][0] = sX[(rb + lr    ) * LDS_STRIDE + kk + lc    ];
                af[mt][1] = sX[(rb + lr + 8) * LDS_STRIDE + kk + lc    ];
                af[mt][2] = sX[(rb + lr    ) * LDS_STRIDE + kk + lc + 4];
                af[mt][3] = sX[(rb + lr + 8) * LDS_STRIDE + kk + lc + 4];
            }
#pragma unroll
            for (int nt = 0; nt < 4; nt++) {
                const int nb = wn + nt * 8;
                bf[nt][0] = sW[(nb + lr) * LDS_STRIDE + kk + lc    ];
                bf[nt][1] = sW[(nb + lr) * LDS_STRIDE + kk + lc + 4];
            }
#pragma unroll
            for (int mt = 0; mt < 4; mt++)
#pragma unroll
                for (int nt = 0; nt < 4; nt++)
                    mma_tf32(d[mt][nt][0], d[mt][nt][1], d[mt][nt][2], d[mt][nt][3],
                             af[mt][0], af[mt][1], af[mt][2], af[mt][3],
                             bf[nt][0], bf[nt][1]);
        }
        __syncthreads();
    }

    // Epilogue: bias + store. d0,d1 -> (row, col..col+1); d2,d3 -> (row+8, ...).
#pragma unroll
    for (int mt = 0; mt < 4; mt++) {
        const int r0 = bm + wm + mt * 16 + lr;
#pragma unroll
        for (int nt = 0; nt < 4; nt++) {
            const int cl = wn + nt * 8 + lc * 2;  // col within CTA tile
            float2 v0, v1;
            v0.x = d[mt][nt][0] + sBias[cl];
            v0.y = d[mt][nt][1] + sBias[cl + 1];
            v1.x = d[mt][nt][2] + sBias[cl];
            v1.y = d[mt][nt][3] + sBias[cl + 1];
            *(float2*)(C + (size_t)r0 * N3 + bn + cl) = v0;
            *(float2*)(C + (size_t)(r0 + 8) * N3 + bn + cl) = v1;
        }
    }
}

// ---------------------------------------------------------------------------
// Kernel 2: flash-style attention, FFMA2 math (unchanged from R2).
// ---------------------------------------------------------------------------
__global__ __launch_bounds__(128) void attn_kernel(
    const float* __restrict__ qkv,   // [MM, N3]
    float* __restrict__ out)         // [MM, DD]
{
    __shared__ float smemf[2 * 64 * 68];
#define KS(j,d) smemf[(j) * 68 + (d)]
#define VS(j,d) smemf[64 * 68 + (j) * 68 + (d)]

    const int qtile = blockIdx.x;
    const int h     = blockIdx.y;
    const int b     = blockIdx.z;
    const int t     = threadIdx.x;

    const float scale = 0.125f;
    const int qrow = qtile * 128 + t;

    const float* qptr = qkv + ((size_t)(b * LL + qrow)) * N3 + h * HD;
    u64 qp[32];
    {
        const u64 sc2 = pack2(scale, scale);
#pragma unroll
        for (int i = 0; i < 16; i++) {
            ulonglong2 v = *(const ulonglong2*)(qptr + i * 4);
            qp[2 * i + 0] = fmul2(v.x, sc2);
            qp[2 * i + 1] = fmul2(v.y, sc2);
        }
    }

    u64 o[32];
#pragma unroll
    for (int i = 0; i < 32; i++) o[i] = 0ULL;
    float m = -1e30f;
    float l = 0.f;

    const int cr = t >> 4;
    const int cc = t & 15;

    for (int kt = 0; kt < LL / 64; kt++) {
        __syncthreads();
#pragma unroll
        for (int pass = 0; pass < 8; pass++) {
            int row = pass * 8 + cr;
            int kl  = kt * 64 + row;
            const float* kp = qkv + ((size_t)(b * LL + kl)) * N3 + DD + h * HD + cc * 4;
            float4 k4 = *(const float4*)kp;
            float4 v4 = *(const float4*)(kp + DD);
            *(float4*)&KS(row, cc * 4) = k4;
            *(float4*)&VS(row, cc * 4) = v4;
        }
        __syncthreads();

        float s[64];
#pragma unroll 2
        for (int j = 0; j < 64; j++) {
            const ulonglong2* kr = (const ulonglong2*)&KS(j, 0);
            u64 a0 = 0ULL, a1 = 0ULL, a2 = 0ULL, a3 = 0ULL;
#pragma unroll
            for (int q4 = 0; q4 < 16; q4 += 2) {
                ulonglong2 k0 = kr[q4];
                ulonglong2 k1 = kr[q4 + 1];
                a0 = ffma2(qp[2 * q4 + 0], k0.x, a0);
                a1 = ffma2(qp[2 * q4 + 1], k0.y, a1);
                a2 = ffma2(qp[2 * q4 + 2], k1.x, a2);
                a3 = ffma2(qp[2 * q4 + 3], k1.y, a3);
            }
            u64 tsum = fadd2(fadd2(a0, a2), fadd2(a1, a3));
            float lo, hi; unpack2(tsum, lo, hi);
            s[j] = lo + hi;
        }

        float mt = m;
#pragma unroll
        for (int j = 0; j < 64; j++) mt = fmaxf(mt, s[j]);
        float corr = __expf(m - mt);
        m = mt;
        l *= corr;
        {
            u64 corr2 = pack2(corr, corr);
#pragma unroll
            for (int i = 0; i < 32; i++) o[i] = fmul2(o[i], corr2);
        }

#pragma unroll 2
        for (int j = 0; j < 64; j++) {
            float p = __expf(s[j] - mt);
            l += p;
            u64 pj = pack2(p, p);
            const ulonglong2* vrow = (const ulonglong2*)&VS(j, 0);
#pragma unroll
            for (int q4 = 0; q4 < 16; q4++) {
                ulonglong2 vv = vrow[q4];
                o[2 * q4 + 0] = ffma2(pj, vv.x, o[2 * q4 + 0]);
                o[2 * q4 + 1] = ffma2(pj, vv.y, o[2 * q4 + 1]);
            }
        }
    }

    {
        float inv = 1.f / l;
        u64 inv2 = pack2(inv, inv);
#pragma unroll
        for (int i = 0; i < 32; i++) o[i] = fmul2(o[i], inv2);
    }

    __syncthreads();
#pragma unroll
    for (int i = 0; i < 32; i++)
        *(u64*)&smemf[t * 66 + 2 * i] = o[i];
    __syncthreads();
#pragma unroll
    for (int pass = 0; pass < 16; pass++) {
        int row = pass * 8 + cr;
        u64 lo = *(const u64*)&smemf[row * 66 + cc * 4];
        u64 hi = *(const u64*)&smemf[row * 66 + cc * 4 + 2];
        ulonglong2 v; v.x = lo; v.y = hi;
        *(ulonglong2*)(out + ((size_t)(b * LL + qtile * 128 + row)) * DD + h * HD + cc * 4) = v;
    }
#undef KS
#undef VS
}

// ---------------------------------------------------------------------------
extern "C" void kernel_launch(void* const* d_in, const int* in_sizes, int n_in,
                              void* d_out, int out_size)
{
    const float* x    = (const float*)d_in[0];   // [2, 2048, 1024]
    const float* W    = (const float*)d_in[1];   // [3072, 1024]
    const float* bias = (const float*)d_in[2];   // [3072]
    float* out = (float*)d_out;                  // [2, 2048, 1024]

    float* qkv;
    cudaGetSymbolAddress((void**)&qkv, g_qkv);

    dim3 ggrid(N3 / 128, MM / 128);  // (24, 32)
    qkv_gemm_mma<<<ggrid, 256>>>(x, W, bias, qkv);

    dim3 agrid(LL / 128, NH, BB);    // (16, 16, 2)
    attn_kernel<<<agrid, 128>>>(qkv, out);
}

// round 6
// speedup vs baseline: 3.2919x; 2.5781x over previous
#include <cuda_runtime.h>
#include <cuda_bf16.h>
#include <cstdint>

// Problem constants
#define BB 2
#define LL 2048
#define DD 1024
#define NH 16
#define HD 64
#define MM (BB*LL)      // 4096
#define N3 (3*DD)       // 3072
#define KK DD           // 1024

typedef unsigned long long u64;
typedef unsigned int u32;

// ---- tf32 mma.sync helpers ----
__device__ __forceinline__ u32 f2tf32(float f) {
    u32 r; asm("cvt.rna.tf32.f32 %0, %1;" : "=r"(r) : "f"(f)); return r;
}
__device__ __forceinline__ void mma_tf32(float& d0, float& d1, float& d2, float& d3,
                                         u32 a0, u32 a1, u32 a2, u32 a3,
                                         u32 b0, u32 b1) {
    asm volatile(
        "mma.sync.aligned.m16n8k8.row.col.f32.tf32.tf32.f32 "
        "{%0,%1,%2,%3}, {%4,%5,%6,%7}, {%8,%9}, {%0,%1,%2,%3};"
        : "+f"(d0), "+f"(d1), "+f"(d2), "+f"(d3)
        : "r"(a0), "r"(a1), "r"(a2), "r"(a3), "r"(b0), "r"(b1));
}
__device__ __forceinline__ float ex2(float x) {
    float y; asm("ex2.approx.f32 %0, %1;" : "=f"(y) : "f"(x)); return y;
}

// Scratch for qkv = x @ W^T + b : [4096, 3072] fp32
__device__ float g_qkv[(size_t)MM * N3];

// ---------------------------------------------------------------------------
// Kernel 1: QKV GEMM on mma.sync tf32 (unchanged from R4).
// ---------------------------------------------------------------------------
#define LDS_STRIDE 36

__global__ __launch_bounds__(256) void qkv_gemm_mma(
    const float* __restrict__ x,
    const float* __restrict__ W,
    const float* __restrict__ bias,
    float* __restrict__ C)
{
    __shared__ u32 sX[128 * LDS_STRIDE];
    __shared__ u32 sW[128 * LDS_STRIDE];
    __shared__ float sBias[128];

    const int bm = blockIdx.y * 128;
    const int bn = blockIdx.x * 128;
    const int tid  = threadIdx.x;
    const int wid  = tid >> 5;
    const int lane = tid & 31;
    const int wm = (wid >> 2) * 64;
    const int wn = (wid & 3) * 32;
    const int lr = lane >> 2;
    const int lc = lane & 3;

    float d[4][4][4];
#pragma unroll
    for (int mt = 0; mt < 4; mt++)
#pragma unroll
        for (int nt = 0; nt < 4; nt++)
#pragma unroll
            for (int r = 0; r < 4; r++) d[mt][nt][r] = 0.f;

    if (tid < 128) sBias[tid] = bias[bn + tid];

    for (int c = 0; c < KK / 32; c++) {
        const int k0 = c * 32;
#pragma unroll
        for (int i = 0; i < 4; i++) {
            int idx = tid + i * 256;
            int row = idx >> 3;
            int f4  = idx & 7;
            float4 xa = *(const float4*)(x + (size_t)(bm + row) * KK + k0 + f4 * 4);
            float4 wa = *(const float4*)(W + (size_t)(bn + row) * KK + k0 + f4 * 4);
            uint4 xt = make_uint4(f2tf32(xa.x), f2tf32(xa.y), f2tf32(xa.z), f2tf32(xa.w));
            uint4 wt = make_uint4(f2tf32(wa.x), f2tf32(wa.y), f2tf32(wa.z), f2tf32(wa.w));
            *(uint4*)&sX[row * LDS_STRIDE + f4 * 4] = xt;
            *(uint4*)&sW[row * LDS_STRIDE + f4 * 4] = wt;
        }
        __syncthreads();

#pragma unroll
        for (int ks = 0; ks < 4; ks++) {
            const int kk = ks * 8;
            u32 af[4][4];
            u32 bf[4][2];
#pragma unroll
            for (int mt = 0; mt < 4; mt++) {
                const int rb = wm + mt * 16;
                af[mt][0] = sX[(rb + lr    ) * LDS_STRIDE + kk + lc    ];
                af[mt][1] = sX[(rb + lr + 8) * LDS_STRIDE + kk + lc    ];
                af[mt][2] = sX[(rb + lr    ) * LDS_STRIDE + kk + lc + 4];
                af[mt][3] = sX[(rb + lr + 8) * LDS_STRIDE + kk + lc + 4];
            }
#pragma unroll
            for (int nt = 0; nt < 4; nt++) {
                const int nb = wn + nt * 8;
                bf[nt][0] = sW[(nb + lr) * LDS_STRIDE + kk + lc    ];
                bf[nt][1] = sW[(nb + lr) * LDS_STRIDE + kk + lc + 4];
            }
#pragma unroll
            for (int mt = 0; mt < 4; mt++)
#pragma unroll
                for (int nt = 0; nt < 4; nt++)
                    mma_tf32(d[mt][nt][0], d[mt][nt][1], d[mt][nt][2], d[mt][nt][3],
                             af[mt][0], af[mt][1], af[mt][2], af[mt][3],
                             bf[nt][0], bf[nt][1]);
        }
        __syncthreads();
    }

#pragma unroll
    for (int mt = 0; mt < 4; mt++) {
        const int r0 = bm + wm + mt * 16 + lr;
#pragma unroll
        for (int nt = 0; nt < 4; nt++) {
            const int cl = wn + nt * 8 + lc * 2;
            float2 v0, v1;
            v0.x = d[mt][nt][0] + sBias[cl];
            v0.y = d[mt][nt][1] + sBias[cl + 1];
            v1.x = d[mt][nt][2] + sBias[cl];
            v1.y = d[mt][nt][3] + sBias[cl + 1];
            *(float2*)(C + (size_t)r0 * N3 + bn + cl) = v0;
            *(float2*)(C + (size_t)(r0 + 8) * N3 + bn + cl) = v1;
        }
    }
}

// ---------------------------------------------------------------------------
// Kernel 2: flash attention on mma.sync tf32.
// Grid (16,16,2), 256 threads = 8 warps. q-tile 128 (16 rows/warp), kv-tile 64.
// K smem stride 68, V smem stride 72 (bank-free B-fragment access).
// P is re-laid from C-fragment to A-fragment layout via lane-quad shuffles.
// ---------------------------------------------------------------------------
#define KSTR 68
#define VSTR 72

__global__ __launch_bounds__(256) void attn_mma(
    const float* __restrict__ qkv,   // [MM, N3]
    float* __restrict__ out)         // [MM, DD]
{
    __shared__ u32 smemPool[64 * KSTR + 64 * VSTR];   // 35840 B
    u32* sK = smemPool;                 // [64 kv][64 d] tf32, stride 68
    u32* sV = smemPool + 64 * KSTR;     // [64 kv][64 d] tf32, stride 72

    const int qtile = blockIdx.x;   // 0..15
    const int h     = blockIdx.y;
    const int b     = blockIdx.z;
    const int tid   = threadIdx.x;
    const int wid   = tid >> 5;
    const int lane  = tid & 31;
    const int lr    = lane >> 2;    // 0..7
    const int lc    = lane & 3;     // 0..3

    const float qs = 0.18033688011110793f;  // 0.125 * log2(e)

    // ---- load Q fragments (resident for whole kernel) ----
    const int row0 = qtile * 128 + wid * 16;
    const float* q0 = qkv + ((size_t)(b * LL + row0 + lr)) * N3 + h * HD;
    const float* q1 = q0 + 8 * (size_t)N3;
    u32 qa[8][4];
#pragma unroll
    for (int kst = 0; kst < 8; kst++) {
        int kk = kst * 8;
        qa[kst][0] = f2tf32(q0[kk + lc    ] * qs);
        qa[kst][1] = f2tf32(q1[kk + lc    ] * qs);
        qa[kst][2] = f2tf32(q0[kk + lc + 4] * qs);
        qa[kst][3] = f2tf32(q1[kk + lc + 4] * qs);
    }

    float o[8][4];
#pragma unroll
    for (int dt = 0; dt < 8; dt++)
#pragma unroll
        for (int r = 0; r < 4; r++) o[dt][r] = 0.f;
    float m_a = -1e30f, m_b = -1e30f;
    float l_a = 0.f,    l_b = 0.f;

    for (int kt = 0; kt < LL / 64; kt++) {
        __syncthreads();
        // ---- load K,V tiles (64x64 each), convert to tf32 ----
#pragma unroll
        for (int i = 0; i < 4; i++) {
            int idx = tid + i * 256;          // 0..1023 float4 slots
            int row = idx >> 4;               // 0..63
            int f4  = idx & 15;               // 0..15
            const float* kp = qkv + ((size_t)(b * LL + kt * 64 + row)) * N3 + DD + h * HD + f4 * 4;
            float4 k4 = *(const float4*)kp;
            float4 v4 = *(const float4*)(kp + DD);
            uint4 kt4 = make_uint4(f2tf32(k4.x), f2tf32(k4.y), f2tf32(k4.z), f2tf32(k4.w));
            uint4 vt4 = make_uint4(f2tf32(v4.x), f2tf32(v4.y), f2tf32(v4.z), f2tf32(v4.w));
            *(uint4*)&sK[row * KSTR + f4 * 4] = kt4;
            *(uint4*)&sV[row * VSTR + f4 * 4] = vt4;
        }
        __syncthreads();

        // ---- S = Q K^T (scaled, base-2 domain) ----
        float s[8][4];
#pragma unroll
        for (int nt = 0; nt < 8; nt++)
#pragma unroll
            for (int r = 0; r < 4; r++) s[nt][r] = 0.f;

#pragma unroll
        for (int kst = 0; kst < 8; kst++) {
            const int kk = kst * 8;
#pragma unroll
            for (int nt = 0; nt < 8; nt++) {
                u32 b0 = sK[(nt * 8 + lr) * KSTR + kk + lc    ];
                u32 b1 = sK[(nt * 8 + lr) * KSTR + kk + lc + 4];
                mma_tf32(s[nt][0], s[nt][1], s[nt][2], s[nt][3],
                         qa[kst][0], qa[kst][1], qa[kst][2], qa[kst][3], b0, b1);
            }
        }

        // ---- online softmax (rows lr -> a, lr+8 -> b) ----
        float mx_a = -1e30f, mx_b = -1e30f;
#pragma unroll
        for (int nt = 0; nt < 8; nt++) {
            mx_a = fmaxf(mx_a, fmaxf(s[nt][0], s[nt][1]));
            mx_b = fmaxf(mx_b, fmaxf(s[nt][2], s[nt][3]));
        }
        mx_a = fmaxf(mx_a, __shfl_xor_sync(0xffffffffu, mx_a, 1));
        mx_a = fmaxf(mx_a, __shfl_xor_sync(0xffffffffu, mx_a, 2));
        mx_b = fmaxf(mx_b, __shfl_xor_sync(0xffffffffu, mx_b, 1));
        mx_b = fmaxf(mx_b, __shfl_xor_sync(0xffffffffu, mx_b, 2));

        float nm_a = fmaxf(m_a, mx_a);
        float nm_b = fmaxf(m_b, mx_b);
        float ca = ex2(m_a - nm_a);
        float cb = ex2(m_b - nm_b);
        m_a = nm_a; m_b = nm_b;
        l_a *= ca;  l_b *= cb;
#pragma unroll
        for (int dt = 0; dt < 8; dt++) {
            o[dt][0] *= ca; o[dt][1] *= ca;
            o[dt][2] *= cb; o[dt][3] *= cb;
        }

        // p = 2^(s-m); accumulate l; store tf32 bits in place
        u32 p[8][4];
#pragma unroll
        for (int nt = 0; nt < 8; nt++) {
            float p0 = ex2(s[nt][0] - m_a);
            float p1 = ex2(s[nt][1] - m_a);
            float p2 = ex2(s[nt][2] - m_b);
            float p3 = ex2(s[nt][3] - m_b);
            l_a += p0 + p1;
            l_b += p2 + p3;
            p[nt][0] = f2tf32(p0); p[nt][1] = f2tf32(p1);
            p[nt][2] = f2tf32(p2); p[nt][3] = f2tf32(p3);
        }

        // ---- O += P V : re-lay P via quad shuffles, then mma ----
        const int s0 = lr * 4 + (lc >> 1);
        const int s2 = s0 + 2;
        const bool odd = (lc & 1);
#pragma unroll
        for (int jt = 0; jt < 8; jt++) {
            u32 v00 = __shfl_sync(0xffffffffu, p[jt][0], s0);
            u32 v01 = __shfl_sync(0xffffffffu, p[jt][1], s0);
            u32 v20 = __shfl_sync(0xffffffffu, p[jt][0], s2);
            u32 v21 = __shfl_sync(0xffffffffu, p[jt][1], s2);
            u32 w00 = __shfl_sync(0xffffffffu, p[jt][2], s0);
            u32 w01 = __shfl_sync(0xffffffffu, p[jt][3], s0);
            u32 w20 = __shfl_sync(0xffffffffu, p[jt][2], s2);
            u32 w21 = __shfl_sync(0xffffffffu, p[jt][3], s2);
            u32 a0 = odd ? v01 : v00;   // P(lr,    jt*8+lc)
            u32 a2 = odd ? v21 : v20;   // P(lr,    jt*8+lc+4)
            u32 a1 = odd ? w01 : w00;   // P(lr+8,  jt*8+lc)
            u32 a3 = odd ? w21 : w20;   // P(lr+8,  jt*8+lc+4)
#pragma unroll
            for (int dt = 0; dt < 8; dt++) {
                u32 b0 = sV[(jt * 8 + lc    ) * VSTR + dt * 8 + lr];
                u32 b1 = sV[(jt * 8 + lc + 4) * VSTR + dt * 8 + lr];
                mma_tf32(o[dt][0], o[dt][1], o[dt][2], o[dt][3],
                         a0, a1, a2, a3, b0, b1);
            }
        }
    }

    // ---- final l reduction + normalize ----
    l_a += __shfl_xor_sync(0xffffffffu, l_a, 1);
    l_a += __shfl_xor_sync(0xffffffffu, l_a, 2);
    l_b += __shfl_xor_sync(0xffffffffu, l_b, 1);
    l_b += __shfl_xor_sync(0xffffffffu, l_b, 2);
    float inv_a = 1.f / l_a;
    float inv_b = 1.f / l_b;

    // ---- stage O to smem (stride 68) then coalesced store ----
    float* stage = (float*)smemPool;   // 128 x 68 floats = 34816 B, fits pool
    __syncthreads();
    {
        const int ra = wid * 16 + lr;
        const int rb = ra + 8;
#pragma unroll
        for (int dt = 0; dt < 8; dt++) {
            float2 va, vb;
            va.x = o[dt][0] * inv_a; va.y = o[dt][1] * inv_a;
            vb.x = o[dt][2] * inv_b; vb.y = o[dt][3] * inv_b;
            *(float2*)&stage[ra * 68 + dt * 8 + lc * 2] = va;
            *(float2*)&stage[rb * 68 + dt * 8 + lc * 2] = vb;
        }
    }
    __syncthreads();
    {
        const int cr = tid >> 4;     // 0..15
        const int cc = tid & 15;     // 0..15
#pragma unroll
        for (int pass = 0; pass < 8; pass++) {
            int row = pass * 16 + cr;
            float4 v = *(const float4*)&stage[row * 68 + cc * 4];
            *(float4*)(out + ((size_t)(b * LL + qtile * 128 + row)) * DD + h * HD + cc * 4) = v;
        }
    }
}

// ---------------------------------------------------------------------------
extern "C" void kernel_launch(void* const* d_in, const int* in_sizes, int n_in,
                              void* d_out, int out_size)
{
    const float* x    = (const float*)d_in[0];
    const float* W    = (const float*)d_in[1];
    const float* bias = (const float*)d_in[2];
    float* out = (float*)d_out;

    float* qkv;
    cudaGetSymbolAddress((void**)&qkv, g_qkv);

    dim3 ggrid(N3 / 128, MM / 128);  // (24, 32)
    qkv_gemm_mma<<<ggrid, 256>>>(x, W, bias, qkv);

    dim3 agrid(LL / 128, NH, BB);    // (16, 16, 2)
    attn_mma<<<agrid, 256>>>(qkv, out);
}

// round 7
// speedup vs baseline: 3.7296x; 1.1330x over previous
#include <cuda_runtime.h>
#include <cuda_bf16.h>
#include <cstdint>

// Problem constants
#define BB 2
#define LL 2048
#define DD 1024
#define NH 16
#define HD 64
#define MM (BB*LL)      // 4096
#define N3 (3*DD)       // 3072
#define KK DD           // 1024

typedef unsigned long long u64;
typedef unsigned int u32;

// ---- tf32 mma.sync helpers ----
__device__ __forceinline__ u32 f2tf32(float f) {
    u32 r; asm("cvt.rna.tf32.f32 %0, %1;" : "=r"(r) : "f"(f)); return r;
}
__device__ __forceinline__ void mma_tf32(float& d0, float& d1, float& d2, float& d3,
                                         u32 a0, u32 a1, u32 a2, u32 a3,
                                         u32 b0, u32 b1) {
    asm volatile(
        "mma.sync.aligned.m16n8k8.row.col.f32.tf32.tf32.f32 "
        "{%0,%1,%2,%3}, {%4,%5,%6,%7}, {%8,%9}, {%0,%1,%2,%3};"
        : "+f"(d0), "+f"(d1), "+f"(d2), "+f"(d3)
        : "r"(a0), "r"(a1), "r"(a2), "r"(a3), "r"(b0), "r"(b1));
}
__device__ __forceinline__ float ex2(float x) {
    float y; asm("ex2.approx.f32 %0, %1;" : "=f"(y) : "f"(x)); return y;
}
__device__ __forceinline__ u32 smem_u32(const void* p) {
    u32 a;
    asm("{ .reg .u64 t; cvta.to.shared.u64 t, %1; cvt.u32.u64 %0, t; }" : "=r"(a) : "l"(p));
    return a;
}
// ldmatrix x4: four 8x(16B) matrices; for fp32 data each matrix is an 8x4 f32
// quadrant, and the per-thread result is exactly a tf32 mma fragment quadrant.
__device__ __forceinline__ void ldsm_x4(u32& r0, u32& r1, u32& r2, u32& r3, u32 addr) {
    asm volatile("ldmatrix.sync.aligned.m8n8.x4.shared.b16 {%0,%1,%2,%3}, [%4];"
                 : "=r"(r0), "=r"(r1), "=r"(r2), "=r"(r3) : "r"(addr));
}

// Scratch for qkv = x @ W^T + b : [4096, 3072] fp32
__device__ float g_qkv[(size_t)MM * N3];

// ---------------------------------------------------------------------------
// Kernel 1: QKV GEMM, mma.sync tf32, double-buffered K-chunks of 16, ldmatrix.
// CTA 128x128, 256 threads = 8 warps (2m x 4n), warp tile 64x32.
// ---------------------------------------------------------------------------
#define GSTR 20   // smem row stride (floats); 80B row offset -> LDSM conflict-free

__global__ __launch_bounds__(256) void qkv_gemm_mma(
    const float* __restrict__ x,
    const float* __restrict__ W,
    const float* __restrict__ bias,
    float* __restrict__ C)
{
    __shared__ u32 sX[2 * 128 * GSTR];
    __shared__ u32 sW[2 * 128 * GSTR];
    __shared__ float sBias[128];

    const int bm = blockIdx.y * 128;
    const int bn = blockIdx.x * 128;
    const int tid  = threadIdx.x;
    const int wid  = tid >> 5;
    const int lane = tid & 31;
    const int wm = (wid >> 2) * 64;
    const int wn = (wid & 3) * 32;
    const int lr = lane >> 2;
    const int lc = lane & 3;

    // tile-load decomposition: 512 float4 slots per tile, 2 per thread
    const int l_row = tid >> 1;          // 0..127
    const int l_f4  = tid & 1;           // 0..1 (chunk16 = 4 f4; x2 passes)

    const u32 sXa = smem_u32(sX);
    const u32 sWa = smem_u32(sW);

    // ldmatrix lane addressing
    const int lm  = lane >> 3;           // matrix id 0..3
    const int lrw = lane & 7;            // row within matrix
    // A: matrices (rb, kk), (rb+8, kk), (rb, kk+4), (rb+8, kk+4)
    const int a_row = (lm & 1) * 8 + lrw;
    const int a_col = (lm >> 1) * 4;
    // B: matrices (nt, kk), (nt, kk+4), (nt+1, kk), (nt+1, kk+4)
    const int b_nt  = lm >> 1;
    const int b_col = (lm & 1) * 4;

    float d[4][4][4];
#pragma unroll
    for (int mt = 0; mt < 4; mt++)
#pragma unroll
        for (int nt = 0; nt < 4; nt++)
#pragma unroll
            for (int r = 0; r < 4; r++) d[mt][nt][r] = 0.f;

    if (tid < 128) sBias[tid] = bias[bn + tid];

    float4 px[2], pw[2];
    // prefetch chunk 0
#pragma unroll
    for (int i = 0; i < 2; i++) {
        int f4 = l_f4 + i * 2;
        px[i] = *(const float4*)(x + (size_t)(bm + l_row) * KK + f4 * 4);
        pw[i] = *(const float4*)(W + (size_t)(bn + l_row) * KK + f4 * 4);
    }
    // store chunk 0 into buffer 0
#pragma unroll
    for (int i = 0; i < 2; i++) {
        int f4 = l_f4 + i * 2;
        *(uint4*)&sX[l_row * GSTR + f4 * 4] =
            make_uint4(f2tf32(px[i].x), f2tf32(px[i].y), f2tf32(px[i].z), f2tf32(px[i].w));
        *(uint4*)&sW[l_row * GSTR + f4 * 4] =
            make_uint4(f2tf32(pw[i].x), f2tf32(pw[i].y), f2tf32(pw[i].z), f2tf32(pw[i].w));
    }
    __syncthreads();

    for (int c = 0; c < KK / 16; c++) {
        // prefetch chunk c+1 into registers (overlaps with MMA below)
        if (c + 1 < KK / 16) {
            const int k0 = (c + 1) * 16;
#pragma unroll
            for (int i = 0; i < 2; i++) {
                int f4 = l_f4 + i * 2;
                px[i] = *(const float4*)(x + (size_t)(bm + l_row) * KK + k0 + f4 * 4);
                pw[i] = *(const float4*)(W + (size_t)(bn + l_row) * KK + k0 + f4 * 4);
            }
        }

        const u32 bufX = sXa + (u32)((c & 1) * 128 * GSTR * 4);
        const u32 bufW = sWa + (u32)((c & 1) * 128 * GSTR * 4);

#pragma unroll
        for (int ks = 0; ks < 2; ks++) {
            const int kk = ks * 8;
            u32 af[4][4];
            u32 bf[4][2];
#pragma unroll
            for (int mt = 0; mt < 4; mt++) {
                u32 addr = bufX + (u32)(((wm + mt * 16 + a_row) * GSTR + kk + a_col) * 4);
                ldsm_x4(af[mt][0], af[mt][1], af[mt][2], af[mt][3], addr);
            }
#pragma unroll
            for (int np = 0; np < 2; np++) {
                u32 addr = bufW + (u32)(((wn + (np * 2 + b_nt) * 8 + lrw) * GSTR + kk + b_col) * 4);
                ldsm_x4(bf[np * 2][0], bf[np * 2][1], bf[np * 2 + 1][0], bf[np * 2 + 1][1], addr);
            }
#pragma unroll
            for (int mt = 0; mt < 4; mt++)
#pragma unroll
                for (int nt = 0; nt < 4; nt++)
                    mma_tf32(d[mt][nt][0], d[mt][nt][1], d[mt][nt][2], d[mt][nt][3],
                             af[mt][0], af[mt][1], af[mt][2], af[mt][3],
                             bf[nt][0], bf[nt][1]);
        }

        // stage chunk c+1 into the other buffer
        if (c + 1 < KK / 16) {
            u32* dX = sX + ((c + 1) & 1) * 128 * GSTR;
            u32* dW = sW + ((c + 1) & 1) * 128 * GSTR;
#pragma unroll
            for (int i = 0; i < 2; i++) {
                int f4 = l_f4 + i * 2;
                *(uint4*)&dX[l_row * GSTR + f4 * 4] =
                    make_uint4(f2tf32(px[i].x), f2tf32(px[i].y), f2tf32(px[i].z), f2tf32(px[i].w));
                *(uint4*)&dW[l_row * GSTR + f4 * 4] =
                    make_uint4(f2tf32(pw[i].x), f2tf32(pw[i].y), f2tf32(pw[i].z), f2tf32(pw[i].w));
            }
        }
        __syncthreads();
    }

#pragma unroll
    for (int mt = 0; mt < 4; mt++) {
        const int r0 = bm + wm + mt * 16 + lr;
#pragma unroll
        for (int nt = 0; nt < 4; nt++) {
            const int cl = wn + nt * 8 + lc * 2;
            float2 v0, v1;
            v0.x = d[mt][nt][0] + sBias[cl];
            v0.y = d[mt][nt][1] + sBias[cl + 1];
            v1.x = d[mt][nt][2] + sBias[cl];
            v1.y = d[mt][nt][3] + sBias[cl + 1];
            *(float2*)(C + (size_t)r0 * N3 + bn + cl) = v0;
            *(float2*)(C + (size_t)(r0 + 8) * N3 + bn + cl) = v1;
        }
    }
}

// ---------------------------------------------------------------------------
// Kernel 2: flash attention, mma.sync tf32, kv-tile 32, double-buffered,
// ldmatrix for K fragments. 256 threads, q-tile 128.
// ---------------------------------------------------------------------------
#define KSTR 68
#define VSTR 72
#define KV 32

__global__ __launch_bounds__(256) void attn_mma(
    const float* __restrict__ qkv,   // [MM, N3]
    float* __restrict__ out)         // [MM, DD]
{
    __shared__ u32 pool[2 * KV * KSTR + 2 * KV * VSTR];   // 35840 B
    u32* sK = pool;
    u32* sV = pool + 2 * KV * KSTR;
    const u32 sKa = smem_u32(sK);

    const int qtile = blockIdx.x;
    const int h     = blockIdx.y;
    const int b     = blockIdx.z;
    const int tid   = threadIdx.x;
    const int wid   = tid >> 5;
    const int lane  = tid & 31;
    const int lr    = lane >> 2;
    const int lc    = lane & 3;
    const int lm    = lane >> 3;   // ldmatrix matrix id
    const int lrw   = lane & 7;

    const float qs = 0.18033688011110793f;  // 0.125 * log2(e)

    // tile-load decomposition: KV*16*... 512 float4 slots, 2 per thread
    const int l_row = tid >> 3;          // 0..31 (kv row)
    const int l_f4h = tid & 7;           // 0..7; two passes cover f4 0..15

    // ---- Q fragments resident ----
    const int row0 = qtile * 128 + wid * 16;
    const float* q0 = qkv + ((size_t)(b * LL + row0 + lr)) * N3 + h * HD;
    const float* q1 = q0 + 8 * (size_t)N3;
    u32 qa[8][4];
#pragma unroll
    for (int kst = 0; kst < 8; kst++) {
        int kk = kst * 8;
        qa[kst][0] = f2tf32(q0[kk + lc    ] * qs);
        qa[kst][1] = f2tf32(q1[kk + lc    ] * qs);
        qa[kst][2] = f2tf32(q0[kk + lc + 4] * qs);
        qa[kst][3] = f2tf32(q1[kk + lc + 4] * qs);
    }

    float o[8][4];
#pragma unroll
    for (int dt = 0; dt < 8; dt++)
#pragma unroll
        for (int r = 0; r < 4; r++) o[dt][r] = 0.f;
    float m_a = -1e30f, m_b = -1e30f;
    float l_a = 0.f,    l_b = 0.f;

    const float* kvbase = qkv + (size_t)b * LL * N3 + DD + h * HD;

    float4 pk[2], pv[2];
    // prefetch tile 0
#pragma unroll
    for (int i = 0; i < 2; i++) {
        const float* kp = kvbase + (size_t)l_row * N3 + (l_f4h + i * 8) * 4;
        pk[i] = *(const float4*)kp;
        pv[i] = *(const float4*)(kp + DD);
    }
#pragma unroll
    for (int i = 0; i < 2; i++) {
        int f4 = l_f4h + i * 8;
        *(uint4*)&sK[l_row * KSTR + f4 * 4] =
            make_uint4(f2tf32(pk[i].x), f2tf32(pk[i].y), f2tf32(pk[i].z), f2tf32(pk[i].w));
        *(uint4*)&sV[l_row * VSTR + f4 * 4] =
            make_uint4(f2tf32(pv[i].x), f2tf32(pv[i].y), f2tf32(pv[i].z), f2tf32(pv[i].w));
    }
    __syncthreads();

    const int NT = LL / KV;   // 64 tiles
    for (int kt = 0; kt < NT; kt++) {
        // prefetch next tile into regs
        if (kt + 1 < NT) {
            const float* tb = kvbase + (size_t)((kt + 1) * KV) * N3;
#pragma unroll
            for (int i = 0; i < 2; i++) {
                const float* kp = tb + (size_t)l_row * N3 + (l_f4h + i * 8) * 4;
                pk[i] = *(const float4*)kp;
                pv[i] = *(const float4*)(kp + DD);
            }
        }

        const u32 bufK = sKa + (u32)((kt & 1) * KV * KSTR * 4);
        u32* bufV = sV + (kt & 1) * KV * VSTR;

        // ---- S = Q K^T ----
        float s[4][4];
#pragma unroll
        for (int nt = 0; nt < 4; nt++)
#pragma unroll
            for (int r = 0; r < 4; r++) s[nt][r] = 0.f;

#pragma unroll
        for (int kst = 0; kst < 8; kst++) {
            const int kk = kst * 8;
            u32 bf[4][2];
#pragma unroll
            for (int np = 0; np < 2; np++) {
                // matrices: (nt, kk), (nt, kk+4), (nt+1, kk), (nt+1, kk+4)
                int nt0 = np * 2 + (lm >> 1);
                u32 addr = bufK + (u32)(((nt0 * 8 + lrw) * KSTR + kk + (lm & 1) * 4) * 4);
                ldsm_x4(bf[np * 2][0], bf[np * 2][1], bf[np * 2 + 1][0], bf[np * 2 + 1][1], addr);
            }
#pragma unroll
            for (int nt = 0; nt < 4; nt++)
                mma_tf32(s[nt][0], s[nt][1], s[nt][2], s[nt][3],
                         qa[kst][0], qa[kst][1], qa[kst][2], qa[kst][3],
                         bf[nt][0], bf[nt][1]);
        }

        // ---- online softmax ----
        float mx_a = -1e30f, mx_b = -1e30f;
#pragma unroll
        for (int nt = 0; nt < 4; nt++) {
            mx_a = fmaxf(mx_a, fmaxf(s[nt][0], s[nt][1]));
            mx_b = fmaxf(mx_b, fmaxf(s[nt][2], s[nt][3]));
        }
        mx_a = fmaxf(mx_a, __shfl_xor_sync(0xffffffffu, mx_a, 1));
        mx_a = fmaxf(mx_a, __shfl_xor_sync(0xffffffffu, mx_a, 2));
        mx_b = fmaxf(mx_b, __shfl_xor_sync(0xffffffffu, mx_b, 1));
        mx_b = fmaxf(mx_b, __shfl_xor_sync(0xffffffffu, mx_b, 2));

        float nm_a = fmaxf(m_a, mx_a);
        float nm_b = fmaxf(m_b, mx_b);
        float ca = ex2(m_a - nm_a);
        float cb = ex2(m_b - nm_b);
        m_a = nm_a; m_b = nm_b;
        l_a *= ca;  l_b *= cb;
#pragma unroll
        for (int dt = 0; dt < 8; dt++) {
            o[dt][0] *= ca; o[dt][1] *= ca;
            o[dt][2] *= cb; o[dt][3] *= cb;
        }

        u32 p[4][4];
#pragma unroll
        for (int nt = 0; nt < 4; nt++) {
            float p0 = ex2(s[nt][0] - m_a);
            float p1 = ex2(s[nt][1] - m_a);
            float p2 = ex2(s[nt][2] - m_b);
            float p3 = ex2(s[nt][3] - m_b);
            l_a += p0 + p1;
            l_b += p2 + p3;
            p[nt][0] = f2tf32(p0); p[nt][1] = f2tf32(p1);
            p[nt][2] = f2tf32(p2); p[nt][3] = f2tf32(p3);
        }

        // ---- O += P V ----
        const int s0 = lr * 4 + (lc >> 1);
        const int s2 = s0 + 2;
        const bool odd = (lc & 1);
#pragma unroll
        for (int jt = 0; jt < 4; jt++) {
            u32 v00 = __shfl_sync(0xffffffffu, p[jt][0], s0);
            u32 v01 = __shfl_sync(0xffffffffu, p[jt][1], s0);
            u32 v20 = __shfl_sync(0xffffffffu, p[jt][0], s2);
            u32 v21 = __shfl_sync(0xffffffffu, p[jt][1], s2);
            u32 w00 = __shfl_sync(0xffffffffu, p[jt][2], s0);
            u32 w01 = __shfl_sync(0xffffffffu, p[jt][3], s0);
            u32 w20 = __shfl_sync(0xffffffffu, p[jt][2], s2);
            u32 w21 = __shfl_sync(0xffffffffu, p[jt][3], s2);
            u32 a0 = odd ? v01 : v00;
            u32 a2 = odd ? v21 : v20;
            u32 a1 = odd ? w01 : w00;
            u32 a3 = odd ? w21 : w20;
#pragma unroll
            for (int dt = 0; dt < 8; dt++) {
                u32 b0 = bufV[(jt * 8 + lc    ) * VSTR + dt * 8 + lr];
                u32 b1 = bufV[(jt * 8 + lc + 4) * VSTR + dt * 8 + lr];
                mma_tf32(o[dt][0], o[dt][1], o[dt][2], o[dt][3],
                         a0, a1, a2, a3, b0, b1);
            }
        }

        // stage next tile into other buffer
        if (kt + 1 < NT) {
            u32* dK = sK + ((kt + 1) & 1) * KV * KSTR;
            u32* dV = sV + ((kt + 1) & 1) * KV * VSTR;
#pragma unroll
            for (int i = 0; i < 2; i++) {
                int f4 = l_f4h + i * 8;
                *(uint4*)&dK[l_row * KSTR + f4 * 4] =
                    make_uint4(f2tf32(pk[i].x), f2tf32(pk[i].y), f2tf32(pk[i].z), f2tf32(pk[i].w));
                *(uint4*)&dV[l_row * VSTR + f4 * 4] =
                    make_uint4(f2tf32(pv[i].x), f2tf32(pv[i].y), f2tf32(pv[i].z), f2tf32(pv[i].w));
            }
        }
        __syncthreads();
    }

    // ---- final reduce + normalize ----
    l_a += __shfl_xor_sync(0xffffffffu, l_a, 1);
    l_a += __shfl_xor_sync(0xffffffffu, l_a, 2);
    l_b += __shfl_xor_sync(0xffffffffu, l_b, 1);
    l_b += __shfl_xor_sync(0xffffffffu, l_b, 2);
    float inv_a = 1.f / l_a;
    float inv_b = 1.f / l_b;

    // ---- stage O to smem then coalesced store ----
    float* stage = (float*)pool;   // 128 x 68 floats = 34816 B <= pool
    __syncthreads();
    {
        const int ra = wid * 16 + lr;
        const int rb = ra + 8;
#pragma unroll
        for (int dt = 0; dt < 8; dt++) {
            float2 va, vb;
            va.x = o[dt][0] * inv_a; va.y = o[dt][1] * inv_a;
            vb.x = o[dt][2] * inv_b; vb.y = o[dt][3] * inv_b;
            *(float2*)&stage[ra * 68 + dt * 8 + lc * 2] = va;
            *(float2*)&stage[rb * 68 + dt * 8 + lc * 2] = vb;
        }
    }
    __syncthreads();
    {
        const int cr = tid >> 4;
        const int cc = tid & 15;
#pragma unroll
        for (int pass = 0; pass < 8; pass++) {
            int row = pass * 16 + cr;
            float4 v = *(const float4*)&stage[row * 68 + cc * 4];
            *(float4*)(out + ((size_t)(b * LL + qtile * 128 + row)) * DD + h * HD + cc * 4) = v;
        }
    }
}

// ---------------------------------------------------------------------------
extern "C" void kernel_launch(void* const* d_in, const int* in_sizes, int n_in,
                              void* d_out, int out_size)
{
    const float* x    = (const float*)d_in[0];
    const float* W    = (const float*)d_in[1];
    const float* bias = (const float*)d_in[2];
    float* out = (float*)d_out;

    float* qkv;
    cudaGetSymbolAddress((void**)&qkv, g_qkv);

    dim3 ggrid(N3 / 128, MM / 128);  // (24, 32)
    qkv_gemm_mma<<<ggrid, 256>>>(x, W, bias, qkv);

    dim3 agrid(LL / 128, NH, BB);    // (16, 16, 2)
    attn_mma<<<agrid, 256>>>(qkv, out);
}